// round 2
// baseline (speedup 1.0000x reference)
#include <cuda_runtime.h>
#include <math.h>

#define KK 16
#define CC 8
#define HW 65536
#define TILE 128
#define NKC 136   // C + K*C output channels

__device__ float g_P[KK * 64];
__device__ float g_mu[KK * 8];
__device__ float g_c2[KK];

// One thread per mixture component k: invert 8x8 lower-triangular L,
// form precision P = Linv^T Linv, fold log-det + normalizer into one constant.
__global__ void prep_kernel(const float* __restrict__ scale,
                            const float* __restrict__ mean) {
    int k = threadIdx.x;
    if (k >= KK) return;
    const float* L = scale + k * 64;   // scale[k,0,:,:] row-major 8x8

    float Linv[8][8];
    for (int j = 0; j < 8; j++)
        for (int i = 0; i < 8; i++) Linv[i][j] = 0.f;

    // Forward substitution per unit-basis column (only lower triangle of L used,
    // matching scipy solve_triangular(lower=True)).
    for (int j = 0; j < 8; j++) {
        for (int i = j; i < 8; i++) {
            float s = (i == j) ? 1.f : 0.f;
            for (int m = j; m < i; m++) s -= L[i * 8 + m] * Linv[m][j];
            Linv[i][j] = s / L[i * 8 + i];
        }
    }

    float logdet = 0.f;
    for (int i = 0; i < 8; i++) logdet += logf(fabsf(L[i * 8 + i]));

    // P = Linv^T * Linv (symmetric)
    for (int i = 0; i < 8; i++)
        for (int j = 0; j < 8; j++) {
            float s = 0.f;
            int r0 = (i > j) ? i : j;
            for (int r = r0; r < 8; r++) s += Linv[r][i] * Linv[r][j];
            g_P[k * 64 + i * 8 + j] = s;
        }

    for (int c = 0; c < 8; c++) g_mu[k * 8 + c] = mean[k * 8 + c];

    const float LN2PI = 1.8378770664093453f;
    const float LOG2E = 1.4426950408889634f;
    // gauss = 2^( -0.5*log2e*quad + c2 )
    g_c2[k] = (-logdet - 4.0f * LN2PI) * LOG2E;
}

__global__ __launch_bounds__(128)
void main_kernel(const float* __restrict__ x, float* __restrict__ out) {
    __shared__ float sP[KK * 64];      // 4 KB
    __shared__ float sMu[KK * 8];      // 512 B
    __shared__ float sC2[KK];
    __shared__ float xsT[8][TILE];     // channel-major x tile, 4 KB
    __shared__ float sg[KK][TILE];     // gauss per (k, pixel), 8 KB

    const int tid = threadIdx.x;

    // Cooperative constant loads
    for (int i = tid; i < KK * 64; i += 128) sP[i] = g_P[i];
    sMu[tid] = g_mu[tid];              // exactly 128 entries
    if (tid < KK) sC2[tid] = g_c2[tid];

    const int T   = blockIdx.x;        // 4096 tiles of 128 source pixels
    const int bi  = T >> 9;            // image index (512 tiles per image)
    const int tin = T & 511;           // tile index within image
    const long sp = (long)T * TILE + tid;   // this thread's source pixel

    // Load this pixel's 8 channels (two float4s, fully coalesced)
    const float4* xp = reinterpret_cast<const float4*>(x + sp * 8);
    float4 a = xp[0], b = xp[1];
    float xv[8] = {a.x, a.y, a.z, a.w, b.x, b.y, b.z, b.w};
    #pragma unroll
    for (int c = 0; c < 8; c++) xsT[c][tid] = xv[c];
    __syncthreads();

    // Identity x-copy: out[pixel, 0:8]. Pixel stride 136 floats = 544 B
    // (16B aligned, every 32B store fills a full sector).
    float4* op = reinterpret_cast<float4*>(out + sp * NKC);
    op[0] = a;
    op[1] = b;

    // gauss_k = 2^( -0.5*log2e * (d^T P_k d) + c2_k ), exp2 via FMA-pipe poly
    const float NH_LOG2E = -0.7213475204444817f;
    #pragma unroll 1
    for (int k = 0; k < KK; k++) {
        float d[8];
        #pragma unroll
        for (int i = 0; i < 8; i++) d[i] = xv[i] - sMu[k * 8 + i];
        float quad = 0.f;
        #pragma unroll
        for (int i = 0; i < 8; i++) {
            float v = 0.f;
            #pragma unroll
            for (int j = 0; j < 8; j++)
                v = fmaf(sP[k * 64 + i * 8 + j], d[j], v);
            quad = fmaf(v, d[i], quad);
        }
        float t = fmaf(quad, NH_LOG2E, sC2[k]);
        t = fmaxf(t, -120.f);                 // results below 2^-120 -> ~0, safe
        float fi = rintf(t);
        float f  = t - fi;                    // f in [-0.5, 0.5], exact
        float p  = fmaf(f, 0.0013333558f, 0.0096181291f);
        p = fmaf(f, p, 0.0555041087f);
        p = fmaf(f, p, 0.2402265070f);
        p = fmaf(f, p, 0.6931471806f);
        p = fmaf(f, p, 1.0f);
        float sc = __int_as_float(((int)fi + 127) << 23);  // 2^fi, fi in [-120,0]
        sg[k][tid] = p * sc;
    }
    __syncthreads();

    // Scrambled-reshape writes. For this tile, the (k,c) product vector of its
    // 128 pixels is one contiguous 512 B segment in the output:
    //   out[ ((k*8+c)*8 + bi)*512 + tin ][ 8 + j ] ,  j = 0..127
    // One warp per segment -> perfectly coalesced float4 stores.
    const int warp = tid >> 5, lane = tid & 31;
    const long obase = (long)tin * NKC + 8;
    #pragma unroll 4
    for (int i = 0; i < 32; i++) {
        int seg = i * 4 + warp;            // 0..127 == k*8 + c
        int k = seg >> 3, c = seg & 7;
        long A = ((long)(seg * 8 + bi) * 512) * NKC + obase;
        int j = lane * 4;
        float4 g4 = *reinterpret_cast<const float4*>(&sg[k][j]);
        float4 xc = *reinterpret_cast<const float4*>(&xsT[c][j]);
        float4 o;
        o.x = g4.x * xc.x;
        o.y = g4.y * xc.y;
        o.z = g4.z * xc.z;
        o.w = g4.w * xc.w;
        *reinterpret_cast<float4*>(out + A + j) = o;
    }
}

extern "C" void kernel_launch(void* const* d_in, const int* in_sizes, int n_in,
                              void* d_out, int out_size) {
    // Defensive input identification by element count (sizes are distinct):
    // x = 4,194,304 ; scale = 1,024 ; mean = 128
    const float* x = nullptr; const float* scale = nullptr; const float* mean = nullptr;
    for (int i = 0; i < n_in; i++) {
        if (in_sizes[i] == 4194304)      x     = (const float*)d_in[i];
        else if (in_sizes[i] == 1024)    scale = (const float*)d_in[i];
        else if (in_sizes[i] == 128)     mean  = (const float*)d_in[i];
    }
    float* out = (float*)d_out;

    prep_kernel<<<1, 32>>>(scale, mean);
    main_kernel<<<4096, 128>>>(x, out);
}

// round 3
// speedup vs baseline: 1.3932x; 1.3932x over previous
#include <cuda_runtime.h>
#include <math.h>

#define KK 16
#define CC 8
#define TILE 128
#define NKC 136            // C + K*C output channels
#define PKSTRIDE 64        // padded per-k param record (floats)

// Packed per-k params: [0..7]=bias b=-Linv*mu, [8]=c2 (log-space const),
// [9..11]=pad, [12+rowf4[i]*4 + j] = Linv[i][j] (row i padded to float4).
__device__ float g_pk[KK * PKSTRIDE];

__global__ void prep_kernel(const float* __restrict__ scale,
                            const float* __restrict__ mean) {
    int k = threadIdx.x;
    if (k >= KK) return;
    const float* L = scale + k * 64;

    float Linv[8][8];
    for (int j = 0; j < 8; j++)
        for (int i = 0; i < 8; i++) Linv[i][j] = 0.f;

    // Forward substitution (lower triangle only, matches solve_triangular lower=True)
    for (int j = 0; j < 8; j++) {
        for (int i = j; i < 8; i++) {
            float s = (i == j) ? 1.f : 0.f;
            for (int m = j; m < i; m++) s -= L[i * 8 + m] * Linv[m][j];
            Linv[i][j] = s / L[i * 8 + i];
        }
    }

    float logdet = 0.f;
    for (int i = 0; i < 8; i++) logdet += logf(fabsf(L[i * 8 + i]));

    float* pk = g_pk + k * PKSTRIDE;
    for (int i = 0; i < PKSTRIDE; i++) pk[i] = 0.f;

    // bias = -Linv * mu
    for (int i = 0; i < 8; i++) {
        float s = 0.f;
        for (int j = 0; j <= i; j++) s -= Linv[i][j] * mean[k * 8 + j];
        pk[i] = s;
    }

    const float LN2PI = 1.8378770664093453f;
    const float LOG2E = 1.4426950408889634f;
    pk[8] = (-logdet - 4.0f * LN2PI) * LOG2E;   // gauss = 2^(-0.5*log2e*quad + c2)

    const int rowf4[8] = {0, 1, 2, 3, 4, 6, 8, 10};
    for (int i = 0; i < 8; i++)
        for (int j = 0; j <= i; j++)
            pk[12 + rowf4[i] * 4 + j] = Linv[i][j];
}

__global__ __launch_bounds__(128)
void main_kernel(const float* __restrict__ x, float* __restrict__ out) {
    __shared__ float sPk[KK * PKSTRIDE];   // 4 KB
    __shared__ float xsT[8][TILE];         // 4 KB channel-major x tile
    __shared__ float sg[KK][TILE];         // 8 KB gauss per (k, pixel)

    const int tid = threadIdx.x;

    for (int i = tid; i < KK * PKSTRIDE; i += 128) sPk[i] = g_pk[i];

    const int T   = blockIdx.x;            // 4096 tiles of 128 pixels
    const int bi  = T >> 9;                // image index
    const int tin = T & 511;               // tile within image
    const long sp = (long)T * TILE + tid;  // source pixel

    const float4* xp = reinterpret_cast<const float4*>(x + sp * 8);
    float4 a = xp[0], b4 = xp[1];
    float xv[8] = {a.x, a.y, a.z, a.w, b4.x, b4.y, b4.z, b4.w};
    #pragma unroll
    for (int c = 0; c < 8; c++) xsT[c][tid] = xv[c];

    // Identity x-copy (544 B pixel stride: 32 B-sector exact, coalesced)
    float4* op = reinterpret_cast<float4*>(out + sp * NKC);
    op[0] = a;
    op[1] = b4;
    __syncthreads();

    const float NH_LOG2E = -0.7213475204444817f;   // -0.5*log2(e)
    #pragma unroll 2
    for (int k = 0; k < KK; k++) {
        const float* pk = &sPk[k * PKSTRIDE];
        #define LD4(o) (*reinterpret_cast<const float4*>(pk + (o)))
        float4 bA = LD4(0), bB = LD4(4), cc = LD4(8);
        float quad;
        {
            float4 r = LD4(12);
            float y = fmaf(r.x, xv[0], bA.x);
            quad = y * y;
        }
        {
            float4 r = LD4(16);
            float y = fmaf(r.y, xv[1], fmaf(r.x, xv[0], bA.y));
            quad = fmaf(y, y, quad);
        }
        {
            float4 r = LD4(20);
            float y = fmaf(r.z, xv[2], fmaf(r.y, xv[1], fmaf(r.x, xv[0], bA.z)));
            quad = fmaf(y, y, quad);
        }
        {
            float4 r = LD4(24);
            float y = fmaf(r.w, xv[3], fmaf(r.z, xv[2],
                      fmaf(r.y, xv[1], fmaf(r.x, xv[0], bA.w))));
            quad = fmaf(y, y, quad);
        }
        {
            float4 r = LD4(28); float4 s = LD4(32);
            float y = fmaf(s.x, xv[4], fmaf(r.w, xv[3], fmaf(r.z, xv[2],
                      fmaf(r.y, xv[1], fmaf(r.x, xv[0], bB.x)))));
            quad = fmaf(y, y, quad);
        }
        {
            float4 r = LD4(36); float4 s = LD4(40);
            float y = fmaf(s.y, xv[5], fmaf(s.x, xv[4], fmaf(r.w, xv[3],
                      fmaf(r.z, xv[2], fmaf(r.y, xv[1],
                      fmaf(r.x, xv[0], bB.y))))));
            quad = fmaf(y, y, quad);
        }
        {
            float4 r = LD4(44); float4 s = LD4(48);
            float y = fmaf(s.z, xv[6], fmaf(s.y, xv[5], fmaf(s.x, xv[4],
                      fmaf(r.w, xv[3], fmaf(r.z, xv[2], fmaf(r.y, xv[1],
                      fmaf(r.x, xv[0], bB.z)))))));
            quad = fmaf(y, y, quad);
        }
        {
            float4 r = LD4(52); float4 s = LD4(56);
            float y = fmaf(s.w, xv[7], fmaf(s.z, xv[6], fmaf(s.y, xv[5],
                      fmaf(s.x, xv[4], fmaf(r.w, xv[3], fmaf(r.z, xv[2],
                      fmaf(r.y, xv[1], fmaf(r.x, xv[0], bB.w))))))));
            quad = fmaf(y, y, quad);
        }
        #undef LD4

        float t = fmaf(quad, NH_LOG2E, cc.x);
        t = fmaxf(t, -120.f);
        float fi = rintf(t);
        float f  = t - fi;                        // in [-0.5, 0.5]
        float p  = fmaf(f, 0.0013333558f, 0.0096181291f);
        p = fmaf(f, p, 0.0555041087f);
        p = fmaf(f, p, 0.2402265070f);
        p = fmaf(f, p, 0.6931471806f);
        p = fmaf(f, p, 1.0f);
        float sc = __int_as_float(((int)fi + 127) << 23);  // 2^fi
        sg[k][tid] = p * sc;
    }
    __syncthreads();

    // Scrambled-reshape epilogue. Segment (k,c) of this tile is a contiguous
    // 512 B run: out[(seg*8+bi)*512*NKC + tin*NKC + 8 + j], j=0..127.
    // Warp caches its 8 x-column float4s once; per k one g4 load, 8 pure STGs.
    const int warp = tid >> 5, lane = tid & 31;
    float4 xc[8];
    #pragma unroll
    for (int c = 0; c < 8; c++)
        xc[c] = *reinterpret_cast<const float4*>(&xsT[c][lane * 4]);

    const int obase = tin * NKC + 8 + lane * 4;
    #pragma unroll
    for (int kk = 0; kk < 4; kk++) {
        int k = warp * 4 + kk;
        float4 g4 = *reinterpret_cast<const float4*>(&sg[k][lane * 4]);
        #pragma unroll
        for (int c = 0; c < 8; c++) {
            int seg = k * 8 + c;
            int A = (seg * 8 + bi) * (512 * NKC) + obase;   // max ~71.2M < 2^31
            float4 o;
            o.x = g4.x * xc[c].x;
            o.y = g4.y * xc[c].y;
            o.z = g4.z * xc[c].z;
            o.w = g4.w * xc[c].w;
            *reinterpret_cast<float4*>(out + A) = o;
        }
    }
}

extern "C" void kernel_launch(void* const* d_in, const int* in_sizes, int n_in,
                              void* d_out, int out_size) {
    // Identify inputs by element count: x=4,194,304; scale=1,024; mean=128
    const float* x = nullptr; const float* scale = nullptr; const float* mean = nullptr;
    for (int i = 0; i < n_in; i++) {
        if (in_sizes[i] == 4194304)      x     = (const float*)d_in[i];
        else if (in_sizes[i] == 1024)    scale = (const float*)d_in[i];
        else if (in_sizes[i] == 128)     mean  = (const float*)d_in[i];
    }
    float* out = (float*)d_out;

    prep_kernel<<<1, 32>>>(scale, mean);
    main_kernel<<<4096, 128>>>(x, out);
}